// round 14
// baseline (speedup 1.0000x reference)
#include <cuda_runtime.h>

#define GSZ   52
#define NANCH 3
#define NCELL (GSZ * GSZ * NANCH)   // 8112
#define REC   85
#define MAXB  64
#define MAXGT 64
#define IMGSZ 416.0f
#define RATIO 8.0f
#define TILE  13
#define TC    (TILE * TILE * NANCH) // 507 records per tile
#define NTX   4
#define NT    (NTX * NTX)           // 16 tiles -> 16 blocks per batch
#define KT    256                   // threads per block (8 warps)
#define KI    2                     // 2 records/thread (512 >= 507)

// ---- scratch (device globals; zero-init at load) ----
__device__ float4   g_gt[MAXB][MAXGT];
__device__ int      g_idx[MAXB][MAXGT];
__device__ int      g_cnt[MAXB];
__device__ unsigned g_mask[MAXB * 256];
__device__ float    g_pA[4][MAXB * NT];
__device__ float    g_pB[MAXB * NT];
__device__ unsigned g_done, g_go, g_done2;

__device__ __forceinline__ float softplusf(float x) {
    return fmaxf(x, 0.0f) + log1pf(expf(-fabsf(x)));
}
__device__ __forceinline__ float sigmoidf_(float x) {
    return 1.0f / (1.0f + expf(-x));
}
__device__ __forceinline__ void select5(int k, float4 v0, float4 v1, float* o) {
    switch (k) {
        case 0: o[0]=v0.x; o[1]=v0.y; o[2]=v0.z; o[3]=v0.w; o[4]=v1.x; break;
        case 1: o[0]=v0.y; o[1]=v0.z; o[2]=v0.w; o[3]=v1.x; o[4]=v1.y; break;
        case 2: o[0]=v0.z; o[1]=v0.w; o[2]=v1.x; o[3]=v1.y; o[4]=v1.z; break;
        default:o[0]=v0.w; o[1]=v1.x; o[2]=v1.y; o[3]=v1.z; o[4]=v1.w; break;
    }
}
__device__ __forceinline__ float warpRedF(float v) {
    #pragma unroll
    for (int o = 16; o > 0; o >>= 1) v += __shfl_down_sync(0xffffffffu, v, o);
    return v;
}

// ===== fused kernel: [conf scan + preds preload] -> grid barrier -> losses
__global__ void __launch_bounds__(KT, 4) kF(const float* __restrict__ preds,
                                            const float* __restrict__ targets,
                                            const float* __restrict__ anchors,
                                            float* __restrict__ out,
                                            int B, unsigned TOTAL) {
    int t    = blockIdx.x;            // tile id in [0,16)
    int b    = blockIdx.y;            // batch
    int tid  = threadIdx.x;
    int lane = tid & 31, wid = tid >> 5;
    int tx0  = (t & (NTX - 1)) * TILE;
    int ty0  = (t >> 2) * TILE;

    // ---------- phase 0a: issue preds-front loads for this tile ----------
    float4 v0[KI], v1[KI];
    int nn[KI];
    #pragma unroll
    for (int i = 0; i < KI; i++) {
        int l = i * KT + tid;
        nn[i] = -1;
        if (l < TC) {
            int cl = l / 3, a = l - cl * 3;
            int cx = tx0 + (cl % TILE);
            int cy = ty0 + (cl / TILE);
            int n  = (cy * GSZ + cx) * 3 + a;
            nn[i] = n;
            size_t rec = (size_t)b * NCELL + n;
            size_t f   = rec * (size_t)REC;
            size_t a4  = (f - (rec & 3)) >> 2;
            v0[i] = __ldg((const float4*)preds + a4);
            v1[i] = __ldg((const float4*)preds + a4 + 1);
        }
    }

    // ---------- phase 0b: conf-scan slice (concurrent with preds loads) ---
    float conf[KI];
    #pragma unroll
    for (int i = 0; i < KI; i++) {
        int n = t * (KT * KI) + i * KT + tid;    // covers [t*512, t*512+512)
        conf[i] = (n < NCELL) ? __ldg(targets + ((size_t)b * NCELL + n) * REC + 4) : 0.0f;
    }
    #pragma unroll
    for (int i = 0; i < KI; i++) {
        int n = t * (KT * KI) + i * KT + tid;    // n <= 8191 -> word <= 255
        unsigned bal = __ballot_sync(0xffffffffu, conf[i] > 0.0f);
        if (lane == 0) g_mask[b * 256 + (n >> 5)] = bal;
        if (conf[i] > 0.0f) {
            int slot = atomicAdd(&g_cnt[b], 1);
            if (slot < MAXGT) {
                const float* r = targets + ((size_t)b * NCELL + n) * REC;
                g_gt[b][slot]  = make_float4(__ldg(r), __ldg(r+1), __ldg(r+2), __ldg(r+3));
                g_idx[b][slot] = n;
            }
        }
    }

    // ---------- grid-wide barrier (512 blocks, all co-resident) ----------
    __threadfence();          // release this thread's global writes
    __syncthreads();
    if (tid == 0) {
        unsigned v = atomicAdd(&g_done, 1u) + 1u;
        if (v == TOTAL) atomicExch(&g_go, 1u);
        while (*(volatile unsigned*)&g_go == 0u) __nanosleep(64);
        __threadfence();      // acquire
    }
    __syncthreads();

    int cnt = min(g_cnt[b], MAXGT);

    // ---------- tile prologue: candidate GTs into smem ----------
    __shared__ float4 sbox[MAXGT];
    __shared__ float  scadd[MAXGT];
    __shared__ float  sanch[6];
    __shared__ int    scand;
    __shared__ float  sred[8];
    __shared__ float  sobj[4][4];

    if (tid == 0) scand = 0;
    if (tid < 6)  sanch[tid] = anchors[tid];
    __syncthreads();

    if (tid < cnt) {
        float4 g = g_gt[b][tid];
        float x_lo = tx0 * 8.0f, x_hi = (tx0 + TILE) * 8.0f;
        float y_lo = ty0 * 8.0f, y_hi = (ty0 + TILE) * 8.0f;
        // necessary for IoU>=0.6: |bx-gx|<=gw/3 (+margin), same in y
        float mx = 0.35f * g.z + 0.02f;
        float my = 0.35f * g.w + 0.02f;
        if (g.x >= x_lo - mx && g.x <= x_hi + mx &&
            g.y >= y_lo - my && g.y <= y_hi + my) {
            int pos = atomicAdd(&scand, 1);
            sbox[pos]  = make_float4(g.x - 0.5f*g.z, g.y - 0.5f*g.w,
                                     g.x + 0.5f*g.z, g.y + 0.5f*g.w);
            scadd[pos] = 0.375f * (g.z * g.w + 1e-9f);
        }
    }
    __syncthreads();
    int ncand = scand;

    // ---------- noobj compute on preloaded registers ----------
    float csum = 0.0f;
    #pragma unroll
    for (int i = 0; i < KI; i++) {
        int n = nn[i];
        if (n < 0) continue;
        unsigned mw = g_mask[b * 256 + (n >> 5)];
        if ((mw >> (n & 31)) & 1u) continue;      // obj cell
        size_t rec = (size_t)b * NCELL + n;
        float p5[5];
        select5((int)(rec & 3), v0[i], v1[i], p5);
        int cl = n / 3, a = n - cl * 3;
        float cx = (float)(cl % GSZ);
        float cy = (float)(cl / GSZ);
        float bx = (sigmoidf_(p5[0]) + cx) * RATIO;
        float by = (sigmoidf_(p5[1]) + cy) * RATIO;
        float bw = expf(p5[2]) * sanch[a * 2 + 0];
        float bh = expf(p5[3]) * sanch[a * 2 + 1];
        float px0 = bx - bw * 0.5f, px1 = bx + bw * 0.5f;
        float py0 = by - bh * 0.5f, py1 = by + bh * 0.5f;
        float apq = 0.375f * (bw * bh);
        bool hit = false;
        for (int j = 0; j < ncand; j++) {
            float4 g = sbox[j];
            float iw = fmaxf(fminf(px1, g.z) - fmaxf(px0, g.x), 0.0f);
            float ih = fmaxf(fminf(py1, g.w) - fmaxf(py0, g.y), 0.0f);
            float inter = iw * ih;
            hit = hit | (inter >= apq + scadd[j]);   // iou >= 0.6
        }
        if (!hit) csum += softplusf(p5[4]);          // conf_t == 0 here
    }

    csum = warpRedF(csum);
    if (lane == 0) sred[wid] = csum;

    // ---------- obj losses: warps 4..7 handle GT slots t*4 + (wid-4) ------
    float txty = 0.f, twth = 0.f, objc = 0.f, clsl = 0.f;
    if (wid >= 4) {
        int slot = t * 4 + (wid - 4);
        if (slot < cnt) {
            int n = g_idx[b][slot];
            size_t f = ((size_t)b * NCELL + n) * REC;
            const float* p = preds + f;
            const float* tg = targets + f;

            float x, tc;
            x = __ldg(p + 5 + lane);  tc = __ldg(tg + 5 + lane);
            clsl += softplusf(x) - x * tc;
            x = __ldg(p + 37 + lane); tc = __ldg(tg + 37 + lane);
            clsl += softplusf(x) - x * tc;
            if (lane < 16) {
                x = __ldg(p + 69 + lane); tc = __ldg(tg + 69 + lane);
                clsl += softplusf(x) - x * tc;
            }

            if (lane == 0) {
                int a    = n % 3;
                int cell = n / 3;
                float fgx = (float)(cell % GSZ);
                float fgy = (float)(cell / GSZ);
                float aw = sanch[a * 2 + 0];
                float ah = sanch[a * 2 + 1];

                float rx = __ldg(p), ry = __ldg(p+1), rw = __ldg(p+2), rh = __ldg(p+3), rc = __ldg(p+4);
                float tx = __ldg(tg), ty = __ldg(tg+1), tw = __ldg(tg+2), th = __ldg(tg+3), cf = __ldg(tg+4);

                float sx = sigmoidf_(rx), sy = sigmoidf_(ry);
                float bx = (sx + fgx) * RATIO;
                float by = (sy + fgy) * RATIO;
                float pxn = bx / RATIO - fgx;
                float pyn = by / RATIO - fgy;
                float txn = tx / RATIO - fgx;
                float tyn = ty / RATIO - fgy;
                float scale = 2.0f - ((tw / IMGSZ) * th) / IMGSZ;
                float dx = pxn - txn, dy = pyn - tyn;
                txty = (dx * dx) * scale + (dy * dy) * scale;

                float bw = expf(rw) * aw, bh = expf(rh) * ah;
                float pwn = bw / aw, phn = bh / ah;
                float twn = tw / aw, thn = th / ah;
                twn = (twn == 0.0f) ? 1.0f : twn;
                thn = (thn == 0.0f) ? 1.0f : thn;
                pwn = (pwn == 0.0f) ? 1.0f : pwn;
                phn = (phn == 0.0f) ? 1.0f : phn;
                twn = logf(fminf(fmaxf(twn, 1e-9f), 1e9f));
                thn = logf(fminf(fmaxf(thn, 1e-9f), 1e9f));
                pwn = logf(fminf(fmaxf(pwn, 1e-9f), 1e9f));
                phn = logf(fminf(fmaxf(phn, 1e-9f), 1e9f));
                float dw = pwn - twn, dh = phn - thn;
                twth = (dw * dw) * scale + (dh * dh) * scale;

                objc = softplusf(rc) - rc * cf;
            }
        }
        clsl = warpRedF(clsl);
        if (lane == 0) {
            sobj[wid-4][0] = txty; sobj[wid-4][1] = twth;
            sobj[wid-4][2] = objc; sobj[wid-4][3] = clsl;
        }
    }
    __syncthreads();

    if (tid == 0) {
        float v = 0.f;
        #pragma unroll
        for (int w = 0; w < 8; w++) v += sred[w];
        g_pB[b * NT + t] = v;
        float a0=0.f, a1=0.f, a2=0.f, a3=0.f;
        #pragma unroll
        for (int w = 0; w < 4; w++) {
            a0 += sobj[w][0]; a1 += sobj[w][1];
            a2 += sobj[w][2]; a3 += sobj[w][3];
        }
        int pb = b * NT + t;
        g_pA[0][pb] = a0; g_pA[1][pb] = a1; g_pA[2][pb] = a2; g_pA[3][pb] = a3;
    }

    // ---------- last-block final reduction ----------
    __shared__ bool amLast;
    if (tid == 0) {
        __threadfence();
        unsigned v = atomicAdd(&g_done2, 1u);
        amLast = (v == TOTAL - 1u);
    }
    __syncthreads();
    if (!amLast) return;

    double s0=0, s1=0, s2=0, s3=0, s4=0;
    for (int i = tid; i < NT * B; i += KT) {
        s2 += (double)g_pB[i];
        s0 += (double)g_pA[0][i];
        s1 += (double)g_pA[1][i];
        s3 += (double)g_pA[2][i];
        s4 += (double)g_pA[3][i];
    }
    __shared__ double sw[8];
    double vals[5] = {s0, s1, s2, s3, s4};
    double res[5];
    #pragma unroll
    for (int j = 0; j < 5; j++) {
        double v = vals[j];
        #pragma unroll
        for (int o = 16; o > 0; o >>= 1) v += __shfl_down_sync(0xffffffffu, v, o);
        if (lane == 0) sw[wid] = v;
        __syncthreads();
        v = (tid < 8) ? sw[tid] : 0.0;
        if (wid == 0) {
            #pragma unroll
            for (int o = 4; o > 0; o >>= 1) v += __shfl_down_sync(0xffffffffu, v, o);
        }
        res[j] = v;
        __syncthreads();
    }
    if (tid == 0) {
        float v0 = (float)(res[0] / (double)B);
        float v1 = (float)(res[1] / (double)B);
        float v2 = (float)(res[2] / (double)B);
        float v3 = (float)(res[3] / (double)B);
        float v4 = (float)(res[4] / (double)B);
        out[0]=v0; out[1]=v1; out[2]=v2; out[3]=v3; out[4]=v4;
        out[5] = (((v0 + v1) + v2) + v3) + v4;
        g_done = 0; g_go = 0; g_done2 = 0;   // reset for next replay
    }
    if (tid < MAXB) g_cnt[tid] = 0;
}

extern "C" void kernel_launch(void* const* d_in, const int* in_sizes, int n_in,
                              void* d_out, int out_size) {
    const float* preds   = (const float*)d_in[0];
    const float* targets = (const float*)d_in[1];
    const float* anchors = (const float*)d_in[2];
    float* out = (float*)d_out;

    int B = in_sizes[0] / (NCELL * REC);
    if (B > MAXB) B = MAXB;

    dim3 grid(NT, B);   // 16 * 32 = 512 blocks; <=64 regs => >=592 co-resident
    kF<<<grid, KT>>>(preds, targets, anchors, out, B, (unsigned)(NT * B));
}

// round 15
// speedup vs baseline: 1.0986x; 1.0986x over previous
#include <cuda_runtime.h>

#define GSZ   52
#define NANCH 3
#define NCELL (GSZ * GSZ * NANCH)   // 8112
#define REC   85
#define MAXB  64
#define MAXGT 64
#define IMGSZ 416.0f
#define RATIO 8.0f
#define TILE  13
#define TC    (TILE * TILE * NANCH) // 507 records per tile
#define NTX   4
#define NT    (NTX * NTX)           // 16 tiles -> 16 blocks per batch
#define KT    256                   // threads per block (8 warps)
#define KI    2                     // 2 records/thread (512 >= 507)

// ---- scratch (device globals; zero-init at load) ----
__device__ float4   g_gt[MAXB][MAXGT];
__device__ int      g_idx[MAXB][MAXGT];
__device__ int      g_cnt[MAXB];
__device__ unsigned g_mask[MAXB * 256];
__device__ float    g_pA[4][MAXB * NT];
__device__ float    g_pB[MAXB * NT];
__device__ unsigned g_bcnt[MAXB];           // per-batch scan arrivals
__device__ unsigned g_done2;

__device__ __forceinline__ float softplusf(float x) {
    return fmaxf(x, 0.0f) + log1pf(expf(-fabsf(x)));
}
__device__ __forceinline__ float sigmoidf_(float x) {
    return 1.0f / (1.0f + expf(-x));
}
__device__ __forceinline__ void select5(int k, float4 v0, float4 v1, float* o) {
    switch (k) {
        case 0: o[0]=v0.x; o[1]=v0.y; o[2]=v0.z; o[3]=v0.w; o[4]=v1.x; break;
        case 1: o[0]=v0.y; o[1]=v0.z; o[2]=v0.w; o[3]=v1.x; o[4]=v1.y; break;
        case 2: o[0]=v0.z; o[1]=v0.w; o[2]=v1.x; o[3]=v1.y; o[4]=v1.z; break;
        default:o[0]=v0.w; o[1]=v1.x; o[2]=v1.y; o[3]=v1.z; o[4]=v1.w; break;
    }
}
__device__ __forceinline__ float warpRedF(float v) {
    #pragma unroll
    for (int o = 16; o > 0; o >>= 1) v += __shfl_down_sync(0xffffffffu, v, o);
    return v;
}

// ===== fused: [conf scan + preds preload] -> per-batch wait -> losses =====
__global__ void __launch_bounds__(KT, 4) kF(const float* __restrict__ preds,
                                            const float* __restrict__ targets,
                                            const float* __restrict__ anchors,
                                            float* __restrict__ out,
                                            int B, unsigned TOTAL) {
    int t    = blockIdx.x;            // tile id in [0,16)
    int b    = blockIdx.y;            // batch
    int tid  = threadIdx.x;
    int lane = tid & 31, wid = tid >> 5;
    int tx0  = (t & (NTX - 1)) * TILE;
    int ty0  = (t >> 2) * TILE;

    // ---------- phase 0a: conf-scan slice [t*512, t*512+512) ----------
    float conf[KI];
    #pragma unroll
    for (int i = 0; i < KI; i++) {
        int n = t * (KT * KI) + i * KT + tid;
        conf[i] = (n < NCELL) ? __ldg(targets + ((size_t)b * NCELL + n) * REC + 4) : 0.0f;
    }

    // ---------- phase 0b: preds-front preload for this tile (concurrent) --
    float4 v0[KI], v1[KI];
    int nn[KI];
    #pragma unroll
    for (int i = 0; i < KI; i++) {
        int l = i * KT + tid;
        nn[i] = -1;
        if (l < TC) {
            int cl = l / 3, a = l - cl * 3;
            int cx = tx0 + (cl % TILE);
            int cy = ty0 + (cl / TILE);
            int n  = (cy * GSZ + cx) * 3 + a;
            nn[i] = n;
            size_t rec = (size_t)b * NCELL + n;
            size_t f   = rec * (size_t)REC;
            size_t a4  = (f - (rec & 3)) >> 2;
            v0[i] = __ldg((const float4*)preds + a4);
            v1[i] = __ldg((const float4*)preds + a4 + 1);
        }
    }

    // ---------- phase 0c: ballot + GT gather ----------
    #pragma unroll
    for (int i = 0; i < KI; i++) {
        int n = t * (KT * KI) + i * KT + tid;    // n <= 8191 -> word <= 255
        unsigned bal = __ballot_sync(0xffffffffu, conf[i] > 0.0f);
        if (lane == 0) g_mask[b * 256 + (n >> 5)] = bal;
        if (conf[i] > 0.0f) {
            int slot = atomicAdd(&g_cnt[b], 1);
            if (slot < MAXGT) {
                const float* r = targets + ((size_t)b * NCELL + n) * REC;
                g_gt[b][slot]  = make_float4(__ldg(r), __ldg(r+1), __ldg(r+2), __ldg(r+3));
                g_idx[b][slot] = n;
            }
        }
    }

    // ---------- per-batch barrier: wait for batch b's 16 scan slices ------
    __threadfence();          // release scan writes (all writer threads)
    __syncthreads();
    if (tid == 0) {
        atomicAdd(&g_bcnt[b], 1u);
        while (*(volatile unsigned*)&g_bcnt[b] < (unsigned)NT) __nanosleep(32);
        __threadfence();      // acquire
    }
    __syncthreads();

    int cnt = min(g_cnt[b], MAXGT);

    // ---------- tile prologue: candidate GTs into smem ----------
    __shared__ float4 sbox[MAXGT];
    __shared__ float  scadd[MAXGT];
    __shared__ float  sanch[6];
    __shared__ int    scand;
    __shared__ float  sred[8];
    __shared__ float  sobj[4][4];

    if (tid == 0) scand = 0;
    if (tid < 6)  sanch[tid] = anchors[tid];
    __syncthreads();

    if (tid < cnt) {
        float4 g = g_gt[b][tid];
        float x_lo = tx0 * 8.0f, x_hi = (tx0 + TILE) * 8.0f;
        float y_lo = ty0 * 8.0f, y_hi = (ty0 + TILE) * 8.0f;
        // necessary for IoU>=0.6: |bx-gx|<=gw/3 (+margin), same in y
        float mx = 0.35f * g.z + 0.02f;
        float my = 0.35f * g.w + 0.02f;
        if (g.x >= x_lo - mx && g.x <= x_hi + mx &&
            g.y >= y_lo - my && g.y <= y_hi + my) {
            int pos = atomicAdd(&scand, 1);
            sbox[pos]  = make_float4(g.x - 0.5f*g.z, g.y - 0.5f*g.w,
                                     g.x + 0.5f*g.z, g.y + 0.5f*g.w);
            scadd[pos] = 0.375f * (g.z * g.w + 1e-9f);
        }
    }
    __syncthreads();
    int ncand = scand;

    // ---------- noobj compute on preloaded registers ----------
    float csum = 0.0f;
    #pragma unroll
    for (int i = 0; i < KI; i++) {
        int n = nn[i];
        if (n < 0) continue;
        unsigned mw = g_mask[b * 256 + (n >> 5)];
        if ((mw >> (n & 31)) & 1u) continue;      // obj cell
        size_t rec = (size_t)b * NCELL + n;
        float p5[5];
        select5((int)(rec & 3), v0[i], v1[i], p5);
        int cl = n / 3, a = n - cl * 3;
        float cx = (float)(cl % GSZ);
        float cy = (float)(cl / GSZ);
        float bx = (sigmoidf_(p5[0]) + cx) * RATIO;
        float by = (sigmoidf_(p5[1]) + cy) * RATIO;
        float bw = expf(p5[2]) * sanch[a * 2 + 0];
        float bh = expf(p5[3]) * sanch[a * 2 + 1];
        float px0 = bx - bw * 0.5f, px1 = bx + bw * 0.5f;
        float py0 = by - bh * 0.5f, py1 = by + bh * 0.5f;
        float apq = 0.375f * (bw * bh);
        bool hit = false;
        for (int j = 0; j < ncand; j++) {
            float4 g = sbox[j];
            float iw = fmaxf(fminf(px1, g.z) - fmaxf(px0, g.x), 0.0f);
            float ih = fmaxf(fminf(py1, g.w) - fmaxf(py0, g.y), 0.0f);
            float inter = iw * ih;
            hit = hit | (inter >= apq + scadd[j]);   // iou >= 0.6
        }
        if (!hit) csum += softplusf(p5[4]);          // conf_t == 0 here
    }

    csum = warpRedF(csum);
    if (lane == 0) sred[wid] = csum;

    // ---------- obj losses: warps 4..7 handle GT slots t*4 + (wid-4) ------
    float txty = 0.f, twth = 0.f, objc = 0.f, clsl = 0.f;
    if (wid >= 4) {
        int slot = t * 4 + (wid - 4);
        if (slot < cnt) {
            int n = g_idx[b][slot];
            size_t f = ((size_t)b * NCELL + n) * REC;
            const float* p = preds + f;
            const float* tg = targets + f;

            float x, tc;
            x = __ldg(p + 5 + lane);  tc = __ldg(tg + 5 + lane);
            clsl += softplusf(x) - x * tc;
            x = __ldg(p + 37 + lane); tc = __ldg(tg + 37 + lane);
            clsl += softplusf(x) - x * tc;
            if (lane < 16) {
                x = __ldg(p + 69 + lane); tc = __ldg(tg + 69 + lane);
                clsl += softplusf(x) - x * tc;
            }

            if (lane == 0) {
                int a    = n % 3;
                int cell = n / 3;
                float fgx = (float)(cell % GSZ);
                float fgy = (float)(cell / GSZ);
                float aw = sanch[a * 2 + 0];
                float ah = sanch[a * 2 + 1];

                float rx = __ldg(p), ry = __ldg(p+1), rw = __ldg(p+2), rh = __ldg(p+3), rc = __ldg(p+4);
                float tx = __ldg(tg), ty = __ldg(tg+1), tw = __ldg(tg+2), th = __ldg(tg+3), cf = __ldg(tg+4);

                float sx = sigmoidf_(rx), sy = sigmoidf_(ry);
                float bx = (sx + fgx) * RATIO;
                float by = (sy + fgy) * RATIO;
                float pxn = bx / RATIO - fgx;
                float pyn = by / RATIO - fgy;
                float txn = tx / RATIO - fgx;
                float tyn = ty / RATIO - fgy;
                float scale = 2.0f - ((tw / IMGSZ) * th) / IMGSZ;
                float dx = pxn - txn, dy = pyn - tyn;
                txty = (dx * dx) * scale + (dy * dy) * scale;

                float bw = expf(rw) * aw, bh = expf(rh) * ah;
                float pwn = bw / aw, phn = bh / ah;
                float twn = tw / aw, thn = th / ah;
                twn = (twn == 0.0f) ? 1.0f : twn;
                thn = (thn == 0.0f) ? 1.0f : thn;
                pwn = (pwn == 0.0f) ? 1.0f : pwn;
                phn = (phn == 0.0f) ? 1.0f : phn;
                twn = logf(fminf(fmaxf(twn, 1e-9f), 1e9f));
                thn = logf(fminf(fmaxf(thn, 1e-9f), 1e9f));
                pwn = logf(fminf(fmaxf(pwn, 1e-9f), 1e9f));
                phn = logf(fminf(fmaxf(phn, 1e-9f), 1e9f));
                float dw = pwn - twn, dh = phn - thn;
                twth = (dw * dw) * scale + (dh * dh) * scale;

                objc = softplusf(rc) - rc * cf;
            }
        }
        clsl = warpRedF(clsl);
        if (lane == 0) {
            sobj[wid-4][0] = txty; sobj[wid-4][1] = twth;
            sobj[wid-4][2] = objc; sobj[wid-4][3] = clsl;
        }
    }
    __syncthreads();

    if (tid == 0) {
        float v = 0.f;
        #pragma unroll
        for (int w = 0; w < 8; w++) v += sred[w];
        g_pB[b * NT + t] = v;
        float a0=0.f, a1=0.f, a2=0.f, a3=0.f;
        #pragma unroll
        for (int w = 0; w < 4; w++) {
            a0 += sobj[w][0]; a1 += sobj[w][1];
            a2 += sobj[w][2]; a3 += sobj[w][3];
        }
        int pb = b * NT + t;
        g_pA[0][pb] = a0; g_pA[1][pb] = a1; g_pA[2][pb] = a2; g_pA[3][pb] = a3;
    }

    // ---------- last-block final reduction ----------
    __shared__ bool amLast;
    if (tid == 0) {
        __threadfence();
        unsigned v = atomicAdd(&g_done2, 1u);
        amLast = (v == TOTAL - 1u);
    }
    __syncthreads();
    if (!amLast) return;

    double s0=0, s1=0, s2=0, s3=0, s4=0;
    for (int i = tid; i < NT * B; i += KT) {
        s2 += (double)g_pB[i];
        s0 += (double)g_pA[0][i];
        s1 += (double)g_pA[1][i];
        s3 += (double)g_pA[2][i];
        s4 += (double)g_pA[3][i];
    }
    __shared__ double sw[8];
    double vals[5] = {s0, s1, s2, s3, s4};
    double res[5];
    #pragma unroll
    for (int j = 0; j < 5; j++) {
        double v = vals[j];
        #pragma unroll
        for (int o = 16; o > 0; o >>= 1) v += __shfl_down_sync(0xffffffffu, v, o);
        if (lane == 0) sw[wid] = v;
        __syncthreads();
        v = (tid < 8) ? sw[tid] : 0.0;
        if (wid == 0) {
            #pragma unroll
            for (int o = 4; o > 0; o >>= 1) v += __shfl_down_sync(0xffffffffu, v, o);
        }
        res[j] = v;
        __syncthreads();
    }
    if (tid == 0) {
        float v0 = (float)(res[0] / (double)B);
        float v1 = (float)(res[1] / (double)B);
        float v2 = (float)(res[2] / (double)B);
        float v3 = (float)(res[3] / (double)B);
        float v4 = (float)(res[4] / (double)B);
        out[0]=v0; out[1]=v1; out[2]=v2; out[3]=v3; out[4]=v4;
        out[5] = (((v0 + v1) + v2) + v3) + v4;
        g_done2 = 0;
    }
    // reset per-batch state for next replay (after all blocks passed waits)
    if (tid < MAXB) { g_cnt[tid] = 0; g_bcnt[tid] = 0; }
}

extern "C" void kernel_launch(void* const* d_in, const int* in_sizes, int n_in,
                              void* d_out, int out_size) {
    const float* preds   = (const float*)d_in[0];
    const float* targets = (const float*)d_in[1];
    const float* anchors = (const float*)d_in[2];
    float* out = (float*)d_out;

    int B = in_sizes[0] / (NCELL * REC);
    if (B > MAXB) B = MAXB;

    dim3 grid(NT, B);   // 512 blocks; launch_bounds(256,4) => all co-resident
    kF<<<grid, KT>>>(preds, targets, anchors, out, B, (unsigned)(NT * B));
}

// round 16
// speedup vs baseline: 1.1001x; 1.0014x over previous
#include <cuda_runtime.h>

#define GSZ   52
#define NANCH 3
#define NCELL (GSZ * GSZ * NANCH)   // 8112
#define REC   85
#define MAXB  64
#define MAXGT 64
#define IMGSZ 416.0f
#define RATIO 8.0f
#define KAB   8
#define KAT   256
#define KAI   4                     // 8*256*4 = 8192 >= 8112
// kB: small blocks, contiguous record slices, many waves
#define KBT   128                   // 4 warps
#define NSL   64                    // 64 slices * 128 = 8192 >= 8112
#define OBJB  16                    // 16 blocks * 4 warps = 64 slots
#define GBX   (NSL + OBJB)          // 80
#define RPR   (GSZ * NANCH)         // 156 records per grid row

// ---- scratch (device globals; zero-init at load) ----
__device__ float4   g_gt[MAXB][MAXGT];
__device__ int      g_idx[MAXB][MAXGT];
__device__ int      g_cnt[MAXB];
__device__ unsigned g_mask[MAXB * 256];
__device__ float    g_pA[4][MAXB * OBJB];
__device__ float    g_pB[MAXB * NSL];
__device__ unsigned g_done;

__device__ __forceinline__ float softplusf(float x) {
    return fmaxf(x, 0.0f) + log1pf(expf(-fabsf(x)));
}
__device__ __forceinline__ float sigmoidf_(float x) {
    return 1.0f / (1.0f + expf(-x));
}
__device__ __forceinline__ void select5(int k, float4 v0, float4 v1, float* o) {
    switch (k) {
        case 0: o[0]=v0.x; o[1]=v0.y; o[2]=v0.z; o[3]=v0.w; o[4]=v1.x; break;
        case 1: o[0]=v0.y; o[1]=v0.z; o[2]=v0.w; o[3]=v1.x; o[4]=v1.y; break;
        case 2: o[0]=v0.z; o[1]=v0.w; o[2]=v1.x; o[3]=v1.y; o[4]=v1.z; break;
        default:o[0]=v0.w; o[1]=v1.x; o[2]=v1.y; o[3]=v1.z; o[4]=v1.w; break;
    }
}
__device__ __forceinline__ float warpRedF(float v) {
    #pragma unroll
    for (int o = 16; o > 0; o >>= 1) v += __shfl_down_sync(0xffffffffu, v, o);
    return v;
}

// ===== kA: coarsened conf scan -> ballot mask + GT gather =====
__global__ void __launch_bounds__(KAT) kA(const float* __restrict__ targets) {
    int b = blockIdx.y;
    int nbase = blockIdx.x * (KAT * KAI) + threadIdx.x;

    float confv[KAI];
    #pragma unroll
    for (int i = 0; i < KAI; i++) {
        int n = nbase + i * KAT;
        confv[i] = (n < NCELL) ? __ldg(targets + ((size_t)b * NCELL + n) * REC + 4) : 0.0f;
    }

    #pragma unroll
    for (int i = 0; i < KAI; i++) {
        int n = nbase + i * KAT;
        unsigned bal = __ballot_sync(0xffffffffu, confv[i] > 0.0f);
        if ((threadIdx.x & 31) == 0) g_mask[b * 256 + (n >> 5)] = bal;
        if (confv[i] > 0.0f) {
            int slot = atomicAdd(&g_cnt[b], 1);
            if (slot < MAXGT) {
                const float* r = targets + ((size_t)b * NCELL + n) * REC;
                g_gt[b][slot]  = make_float4(__ldg(r), __ldg(r+1), __ldg(r+2), __ldg(r+3));
                g_idx[b][slot] = n;
            }
        }
    }
}

// ===== kB: 128-record slices, 128-thread blocks, many waves ========
__global__ void __launch_bounds__(KBT) kB(const float* __restrict__ preds,
                                          const float* __restrict__ targets,
                                          const float* __restrict__ anchors,
                                          float* __restrict__ out, int B) {
    int b    = blockIdx.y;
    int tid  = threadIdx.x;
    int lane = tid & 31, wid = tid >> 5;
    int cnt  = min(g_cnt[b], MAXGT);

    if (blockIdx.x < NSL) {
        // ---------- noobj slice: records [t*128, t*128+128) ----------
        __shared__ float4 sbox[MAXGT];
        __shared__ float  scadd[MAXGT];
        __shared__ float  sanch[6];
        __shared__ int    scand;
        __shared__ float  sred[4];

        int t  = blockIdx.x;
        int n0 = t * KBT;
        int n  = n0 + tid;

        // slice row span -> pixel y band
        int rlo = n0 / RPR;
        int rhi = min(n0 + KBT - 1, NCELL - 1) / RPR;
        float y_lo = rlo * 8.0f;
        float y_hi = (rhi + 1) * 8.0f;

        if (tid == 0) scand = 0;
        if (tid < 6)  sanch[tid] = anchors[tid];
        __syncthreads();

        if (tid < cnt) {
            float4 g = g_gt[b][tid];
            // necessary for IoU>=0.6: |by-gy| <= gh/3 (+slop)
            float my = 0.35f * g.w + 0.02f;
            if (g.y >= y_lo - my && g.y <= y_hi + my) {
                int pos = atomicAdd(&scand, 1);
                sbox[pos]  = make_float4(g.x - 0.5f*g.z, g.y - 0.5f*g.w,
                                         g.x + 0.5f*g.z, g.y + 0.5f*g.w);
                scadd[pos] = 0.375f * (g.z * g.w + 1e-9f);
            }
        }
        __syncthreads();
        int ncand = scand;

        float contrib = 0.0f;
        if (n < NCELL) {
            size_t rec = (size_t)b * NCELL + n;
            size_t f   = rec * (size_t)REC;
            size_t a4  = (f - (rec & 3)) >> 2;
            float4 v0 = __ldg((const float4*)preds + a4);
            float4 v1 = __ldg((const float4*)preds + a4 + 1);
            unsigned w = g_mask[b * 256 + (n >> 5)];
            if (!((w >> (n & 31)) & 1u)) {
                float p5[5];
                select5((int)(rec & 3), v0, v1, p5);
                int cl = n / 3, a = n - cl * 3;
                float cx = (float)(cl % GSZ);
                float cy = (float)(cl / GSZ);
                float bx = (sigmoidf_(p5[0]) + cx) * RATIO;
                float by = (sigmoidf_(p5[1]) + cy) * RATIO;
                float bw = expf(p5[2]) * sanch[a * 2 + 0];
                float bh = expf(p5[3]) * sanch[a * 2 + 1];
                float px0 = bx - bw * 0.5f, px1 = bx + bw * 0.5f;
                float py0 = by - bh * 0.5f, py1 = by + bh * 0.5f;
                float apq = 0.375f * (bw * bh);
                bool hit = false;
                for (int j = 0; j < ncand; j++) {
                    float4 g = sbox[j];
                    float iw = fmaxf(fminf(px1, g.z) - fmaxf(px0, g.x), 0.0f);
                    float ih = fmaxf(fminf(py1, g.w) - fmaxf(py0, g.y), 0.0f);
                    float inter = iw * ih;
                    hit = hit | (inter >= apq + scadd[j]);   // iou >= 0.6
                }
                if (!hit) contrib = softplusf(p5[4]);        // conf_t == 0 here
            }
        }

        contrib = warpRedF(contrib);
        if (lane == 0) sred[wid] = contrib;
        __syncthreads();
        if (tid == 0) {
            g_pB[b * NSL + t] = sred[0] + sred[1] + sred[2] + sred[3];
        }
    } else {
        // ---------- obj losses: one warp per GT slot ----------
        __shared__ float sredo[4][4];
        int ob   = blockIdx.x - NSL;
        int slot = ob * 4 + wid;

        float txty = 0.f, twth = 0.f, objc = 0.f, clsl = 0.f;

        if (slot < cnt) {
            int n = g_idx[b][slot];
            size_t f = ((size_t)b * NCELL + n) * REC;
            const float* p = preds + f;
            const float* tg = targets + f;

            float x, tc;
            x = __ldg(p + 5 + lane);  tc = __ldg(tg + 5 + lane);
            clsl += softplusf(x) - x * tc;
            x = __ldg(p + 37 + lane); tc = __ldg(tg + 37 + lane);
            clsl += softplusf(x) - x * tc;
            if (lane < 16) {
                x = __ldg(p + 69 + lane); tc = __ldg(tg + 69 + lane);
                clsl += softplusf(x) - x * tc;
            }

            if (lane == 0) {
                int a    = n % 3;
                int cell = n / 3;
                float fgx = (float)(cell % GSZ);
                float fgy = (float)(cell / GSZ);
                float aw = __ldg(anchors + a * 2 + 0);
                float ah = __ldg(anchors + a * 2 + 1);

                float rx = __ldg(p), ry = __ldg(p+1), rw = __ldg(p+2), rh = __ldg(p+3), rc = __ldg(p+4);
                float tx = __ldg(tg), ty = __ldg(tg+1), tw = __ldg(tg+2), th = __ldg(tg+3), cf = __ldg(tg+4);

                float sx = sigmoidf_(rx), sy = sigmoidf_(ry);
                float bx = (sx + fgx) * RATIO;
                float by = (sy + fgy) * RATIO;
                float pxn = bx / RATIO - fgx;
                float pyn = by / RATIO - fgy;
                float txn = tx / RATIO - fgx;
                float tyn = ty / RATIO - fgy;
                float scale = 2.0f - ((tw / IMGSZ) * th) / IMGSZ;
                float dx = pxn - txn, dy = pyn - tyn;
                txty = (dx * dx) * scale + (dy * dy) * scale;

                float bw = expf(rw) * aw, bh = expf(rh) * ah;
                float pwn = bw / aw, phn = bh / ah;
                float twn = tw / aw, thn = th / ah;
                twn = (twn == 0.0f) ? 1.0f : twn;
                thn = (thn == 0.0f) ? 1.0f : thn;
                pwn = (pwn == 0.0f) ? 1.0f : pwn;
                phn = (phn == 0.0f) ? 1.0f : phn;
                twn = logf(fminf(fmaxf(twn, 1e-9f), 1e9f));
                thn = logf(fminf(fmaxf(thn, 1e-9f), 1e9f));
                pwn = logf(fminf(fmaxf(pwn, 1e-9f), 1e9f));
                phn = logf(fminf(fmaxf(phn, 1e-9f), 1e9f));
                float dw = pwn - twn, dh = phn - thn;
                twth = (dw * dw) * scale + (dh * dh) * scale;

                objc = softplusf(rc) - rc * cf;
            }
        }

        clsl = warpRedF(clsl);
        if (lane == 0) {
            sredo[wid][0] = txty; sredo[wid][1] = twth;
            sredo[wid][2] = objc; sredo[wid][3] = clsl;
        }
        __syncthreads();
        if (tid == 0) {
            float a0=0.f, a1=0.f, a2=0.f, a3=0.f;
            #pragma unroll
            for (int w = 0; w < 4; w++) {
                a0 += sredo[w][0]; a1 += sredo[w][1];
                a2 += sredo[w][2]; a3 += sredo[w][3];
            }
            int pb = b * OBJB + ob;
            g_pA[0][pb]=a0; g_pA[1][pb]=a1; g_pA[2][pb]=a2; g_pA[3][pb]=a3;
        }
    }

    // ---- last-block final reduction (tid-0 fence; R12-verified) ----
    __shared__ bool amLast;
    if (tid == 0) {
        __threadfence();
        unsigned v = atomicAdd(&g_done, 1u);
        amLast = (v == (unsigned)(GBX * gridDim.y) - 1u);
    }
    __syncthreads();
    if (!amLast) return;

    double s0=0, s1=0, s2=0, s3=0, s4=0;
    for (int i = tid; i < NSL * B; i += KBT) s2 += (double)g_pB[i];
    for (int i = tid; i < OBJB * B; i += KBT) {
        s0 += (double)g_pA[0][i];
        s1 += (double)g_pA[1][i];
        s3 += (double)g_pA[2][i];
        s4 += (double)g_pA[3][i];
    }
    __shared__ double sw[4];
    double vals[5] = {s0, s1, s2, s3, s4};
    double res[5];
    #pragma unroll
    for (int j = 0; j < 5; j++) {
        double v = vals[j];
        #pragma unroll
        for (int o = 16; o > 0; o >>= 1) v += __shfl_down_sync(0xffffffffu, v, o);
        if (lane == 0) sw[wid] = v;
        __syncthreads();
        if (tid == 0) res[j] = sw[0] + sw[1] + sw[2] + sw[3];
        __syncthreads();
    }
    if (tid == 0) {
        float v0 = (float)(res[0] / (double)B);
        float v1 = (float)(res[1] / (double)B);
        float v2 = (float)(res[2] / (double)B);
        float v3 = (float)(res[3] / (double)B);
        float v4 = (float)(res[4] / (double)B);
        out[0]=v0; out[1]=v1; out[2]=v2; out[3]=v3; out[4]=v4;
        out[5] = (((v0 + v1) + v2) + v3) + v4;
        g_done = 0;
    }
    if (tid < MAXB) g_cnt[tid] = 0;
}

extern "C" void kernel_launch(void* const* d_in, const int* in_sizes, int n_in,
                              void* d_out, int out_size) {
    const float* preds   = (const float*)d_in[0];
    const float* targets = (const float*)d_in[1];
    const float* anchors = (const float*)d_in[2];
    float* out = (float*)d_out;

    int B = in_sizes[0] / (NCELL * REC);
    if (B > MAXB) B = MAXB;

    dim3 gA(KAB, B);
    kA<<<gA, KAT>>>(targets);
    dim3 gB(GBX, B);
    kB<<<gB, KBT>>>(preds, targets, anchors, out, B);
}

// round 17
// speedup vs baseline: 1.2076x; 1.0977x over previous
#include <cuda_runtime.h>

#define GSZ   52
#define NANCH 3
#define NCELL (GSZ * GSZ * NANCH)   // 8112
#define REC   85
#define MAXB  64
#define MAXGT 64
#define IMGSZ 416.0f
#define RATIO 8.0f
#define KAB   8
#define KAT   256
#define KAI   4                     // 8*256*4 = 8192 >= 8112
#define TILE  13
#define TC    (TILE * TILE * NANCH) // 507 records per tile
#define NTX   4
#define NT    (NTX * NTX)           // 16 tiles
#define KBT   256                   // 8 warps
#define KBI   2                     // 256*2 = 512 >= 507
#define OBJB  8                     // 8 blocks * 8 warps = 64 slots
#define GBX   (NT + OBJB)           // 24

// ---- scratch (device globals; zero-init at load) ----
__device__ float4   g_gt[MAXB][MAXGT];
__device__ int      g_idx[MAXB][MAXGT];
__device__ int      g_cnt[MAXB];
__device__ unsigned g_mask[MAXB * 256];
__device__ float    g_pA[4][MAXB * OBJB];
__device__ float    g_pB[MAXB * NT];
__device__ unsigned g_done;

// exact versions (obj path: 1280 records, keep max precision)
__device__ __forceinline__ float softplusf(float x) {
    return fmaxf(x, 0.0f) + log1pf(expf(-fabsf(x)));
}
__device__ __forceinline__ float sigmoidf_(float x) {
    return 1.0f / (1.0f + expf(-x));
}
// fast intrinsic versions (noobj hot path: 260K records)
__device__ __forceinline__ float softplus_fast(float x) {
    return fmaxf(x, 0.0f) + __logf(1.0f + __expf(-fabsf(x)));
}
__device__ __forceinline__ float sigmoid_fast(float x) {
    return __fdividef(1.0f, 1.0f + __expf(-x));
}
__device__ __forceinline__ void select5(int k, float4 v0, float4 v1, float* o) {
    switch (k) {
        case 0: o[0]=v0.x; o[1]=v0.y; o[2]=v0.z; o[3]=v0.w; o[4]=v1.x; break;
        case 1: o[0]=v0.y; o[1]=v0.z; o[2]=v0.w; o[3]=v1.x; o[4]=v1.y; break;
        case 2: o[0]=v0.z; o[1]=v0.w; o[2]=v1.x; o[3]=v1.y; o[4]=v1.z; break;
        default:o[0]=v0.w; o[1]=v1.x; o[2]=v1.y; o[3]=v1.z; o[4]=v1.w; break;
    }
}
__device__ __forceinline__ float warpRedF(float v) {
    #pragma unroll
    for (int o = 16; o > 0; o >>= 1) v += __shfl_down_sync(0xffffffffu, v, o);
    return v;
}

// ===== kA: coarsened conf scan -> ballot mask + GT gather =====
__global__ void __launch_bounds__(KAT) kA(const float* __restrict__ targets) {
    int b = blockIdx.y;
    int nbase = blockIdx.x * (KAT * KAI) + threadIdx.x;

    float confv[KAI];
    #pragma unroll
    for (int i = 0; i < KAI; i++) {
        int n = nbase + i * KAT;
        confv[i] = (n < NCELL) ? __ldg(targets + ((size_t)b * NCELL + n) * REC + 4) : 0.0f;
    }

    #pragma unroll
    for (int i = 0; i < KAI; i++) {
        int n = nbase + i * KAT;
        unsigned bal = __ballot_sync(0xffffffffu, confv[i] > 0.0f);
        if ((threadIdx.x & 31) == 0) g_mask[b * 256 + (n >> 5)] = bal;
        if (confv[i] > 0.0f) {
            int slot = atomicAdd(&g_cnt[b], 1);
            if (slot < MAXGT) {
                const float* r = targets + ((size_t)b * NCELL + n) * REC;
                g_gt[b][slot]  = make_float4(__ldg(r), __ldg(r+1), __ldg(r+2), __ldg(r+3));
                g_idx[b][slot] = n;
            }
        }
    }
}

// ===== kB: 13x13 noobj tiles (fast intrinsics) + obj + reduce =====
__global__ void __launch_bounds__(KBT) kB(const float* __restrict__ preds,
                                          const float* __restrict__ targets,
                                          const float* __restrict__ anchors,
                                          float* __restrict__ out, int B) {
    int b    = blockIdx.y;
    int tid  = threadIdx.x;
    int lane = tid & 31, wid = tid >> 5;
    int cnt  = min(g_cnt[b], MAXGT);

    if (blockIdx.x < NT) {
        // ---------- noobj tile: cells [tx0,tx0+13) x [ty0,ty0+13) ----------
        __shared__ float4 sbox[MAXGT];
        __shared__ float  scadd[MAXGT];
        __shared__ float  sanch[6];
        __shared__ int    scand;
        __shared__ float  sred[8];

        int tile = blockIdx.x;
        int tx0  = (tile & (NTX - 1)) * TILE;
        int ty0  = (tile >> 2) * TILE;

        if (tid == 0) scand = 0;
        if (tid < 6)  sanch[tid] = anchors[tid];
        __syncthreads();

        if (tid < cnt) {
            float4 g = g_gt[b][tid];
            float x_lo = tx0 * 8.0f, x_hi = (tx0 + TILE) * 8.0f;
            float y_lo = ty0 * 8.0f, y_hi = (ty0 + TILE) * 8.0f;
            // necessary for IoU>=0.6: |bx-gx|<=gw/3 (+margin), same in y
            float mx = 0.35f * g.z + 0.02f;
            float my = 0.35f * g.w + 0.02f;
            if (g.x >= x_lo - mx && g.x <= x_hi + mx &&
                g.y >= y_lo - my && g.y <= y_hi + my) {
                int pos = atomicAdd(&scand, 1);
                sbox[pos]  = make_float4(g.x - 0.5f*g.z, g.y - 0.5f*g.w,
                                         g.x + 0.5f*g.z, g.y + 0.5f*g.w);
                scadd[pos] = 0.375f * (g.z * g.w + 1e-9f);
            }
        }
        __syncthreads();
        int ncand = scand;

        // ---- phase 1: front-batched loads ----
        float4 v0[KBI], v1[KBI];
        unsigned mw[KBI];
        int nn[KBI];
        #pragma unroll
        for (int i = 0; i < KBI; i++) {
            int l = i * KBT + tid;
            nn[i] = -1;
            if (l < TC) {
                int cl = l / 3, a = l - cl * 3;
                int cx = tx0 + (cl % TILE);
                int cy = ty0 + (cl / TILE);
                int n  = (cy * GSZ + cx) * 3 + a;
                nn[i] = n;
                size_t rec = (size_t)b * NCELL + n;
                size_t f   = rec * (size_t)REC;
                size_t a4  = (f - (rec & 3)) >> 2;
                v0[i] = __ldg((const float4*)preds + a4);
                v1[i] = __ldg((const float4*)preds + a4 + 1);
                mw[i] = g_mask[b * 256 + (n >> 5)];
            }
        }

        // ---- phase 2: compute (fast intrinsics) ----
        float csum = 0.0f;
        #pragma unroll
        for (int i = 0; i < KBI; i++) {
            int n = nn[i];
            if (n < 0) continue;
            if ((mw[i] >> (n & 31)) & 1u) continue;   // obj cell
            size_t rec = (size_t)b * NCELL + n;
            float p5[5];
            select5((int)(rec & 3), v0[i], v1[i], p5);
            int cl = n / 3, a = n - cl * 3;
            float cx = (float)(cl % GSZ);
            float cy = (float)(cl / GSZ);
            float bx = (sigmoid_fast(p5[0]) + cx) * RATIO;
            float by = (sigmoid_fast(p5[1]) + cy) * RATIO;
            float bw = __expf(p5[2]) * sanch[a * 2 + 0];
            float bh = __expf(p5[3]) * sanch[a * 2 + 1];
            float px0 = bx - bw * 0.5f, px1 = bx + bw * 0.5f;
            float py0 = by - bh * 0.5f, py1 = by + bh * 0.5f;
            float apq = 0.375f * (bw * bh);
            bool hit = false;
            for (int j = 0; j < ncand; j++) {
                float4 g = sbox[j];
                float iw = fmaxf(fminf(px1, g.z) - fmaxf(px0, g.x), 0.0f);
                float ih = fmaxf(fminf(py1, g.w) - fmaxf(py0, g.y), 0.0f);
                float inter = iw * ih;
                hit = hit | (inter >= apq + scadd[j]);   // iou >= 0.6
            }
            if (!hit) csum += softplus_fast(p5[4]);      // conf_t == 0 here
        }

        csum = warpRedF(csum);
        if (lane == 0) sred[wid] = csum;
        __syncthreads();
        if (wid == 0) {
            float v = (lane < 8) ? sred[lane] : 0.f;
            #pragma unroll
            for (int o = 4; o > 0; o >>= 1) v += __shfl_down_sync(0xffffffffu, v, o);
            if (lane == 0) g_pB[b * NT + tile] = v;
        }
    } else {
        // ---------- obj losses: one warp per GT slot (exact math) ----------
        __shared__ float sredo[8][4];
        int ob   = blockIdx.x - NT;
        int slot = ob * 8 + wid;

        float txty = 0.f, twth = 0.f, objc = 0.f, clsl = 0.f;

        if (slot < cnt) {
            int n = g_idx[b][slot];
            size_t f = ((size_t)b * NCELL + n) * REC;
            const float* p = preds + f;
            const float* t = targets + f;

            float x, tc;
            x = __ldg(p + 5 + lane);  tc = __ldg(t + 5 + lane);
            clsl += softplusf(x) - x * tc;
            x = __ldg(p + 37 + lane); tc = __ldg(t + 37 + lane);
            clsl += softplusf(x) - x * tc;
            if (lane < 16) {
                x = __ldg(p + 69 + lane); tc = __ldg(t + 69 + lane);
                clsl += softplusf(x) - x * tc;
            }

            if (lane == 0) {
                int a    = n % 3;
                int cell = n / 3;
                float fgx = (float)(cell % GSZ);
                float fgy = (float)(cell / GSZ);
                float aw = __ldg(anchors + a * 2 + 0);
                float ah = __ldg(anchors + a * 2 + 1);

                float rx = __ldg(p), ry = __ldg(p+1), rw = __ldg(p+2), rh = __ldg(p+3), rc = __ldg(p+4);
                float tx = __ldg(t), ty = __ldg(t+1), tw = __ldg(t+2), th = __ldg(t+3), conf = __ldg(t+4);

                float sx = sigmoidf_(rx), sy = sigmoidf_(ry);
                float bx = (sx + fgx) * RATIO;
                float by = (sy + fgy) * RATIO;
                float pxn = bx / RATIO - fgx;
                float pyn = by / RATIO - fgy;
                float txn = tx / RATIO - fgx;
                float tyn = ty / RATIO - fgy;
                float scale = 2.0f - ((tw / IMGSZ) * th) / IMGSZ;
                float dx = pxn - txn, dy = pyn - tyn;
                txty = (dx * dx) * scale + (dy * dy) * scale;

                float bw = expf(rw) * aw, bh = expf(rh) * ah;
                float pwn = bw / aw, phn = bh / ah;
                float twn = tw / aw, thn = th / ah;
                twn = (twn == 0.0f) ? 1.0f : twn;
                thn = (thn == 0.0f) ? 1.0f : thn;
                pwn = (pwn == 0.0f) ? 1.0f : pwn;
                phn = (phn == 0.0f) ? 1.0f : phn;
                twn = logf(fminf(fmaxf(twn, 1e-9f), 1e9f));
                thn = logf(fminf(fmaxf(thn, 1e-9f), 1e9f));
                pwn = logf(fminf(fmaxf(pwn, 1e-9f), 1e9f));
                phn = logf(fminf(fmaxf(phn, 1e-9f), 1e9f));
                float dw = pwn - twn, dh = phn - thn;
                twth = (dw * dw) * scale + (dh * dh) * scale;

                objc = softplusf(rc) - rc * conf;
            }
        }

        txty = warpRedF(txty); twth = warpRedF(twth);
        objc = warpRedF(objc); clsl = warpRedF(clsl);
        if (lane == 0) { sredo[wid][0]=txty; sredo[wid][1]=twth; sredo[wid][2]=objc; sredo[wid][3]=clsl; }
        __syncthreads();
        if (wid == 0) {
            float v0 = (lane < 8) ? sredo[lane][0] : 0.f;
            float v1 = (lane < 8) ? sredo[lane][1] : 0.f;
            float v2 = (lane < 8) ? sredo[lane][2] : 0.f;
            float v3 = (lane < 8) ? sredo[lane][3] : 0.f;
            #pragma unroll
            for (int o = 4; o > 0; o >>= 1) {
                v0 += __shfl_down_sync(0xffffffffu, v0, o);
                v1 += __shfl_down_sync(0xffffffffu, v1, o);
                v2 += __shfl_down_sync(0xffffffffu, v2, o);
                v3 += __shfl_down_sync(0xffffffffu, v3, o);
            }
            if (lane == 0) {
                int pb = b * OBJB + ob;
                g_pA[0][pb]=v0; g_pA[1][pb]=v1; g_pA[2][pb]=v2; g_pA[3][pb]=v3;
            }
        }
    }

    // ---- last-block final reduction (tid-0 fence; R12-verified) ----
    __shared__ bool amLast;
    if (tid == 0) {
        __threadfence();
        unsigned v = atomicAdd(&g_done, 1u);
        amLast = (v == (unsigned)(GBX * gridDim.y) - 1u);
    }
    __syncthreads();
    if (!amLast) return;

    double s0=0, s1=0, s2=0, s3=0, s4=0;
    for (int i = tid; i < NT * B; i += KBT) s2 += (double)g_pB[i];
    for (int i = tid; i < OBJB * B; i += KBT) {
        s0 += (double)g_pA[0][i];
        s1 += (double)g_pA[1][i];
        s3 += (double)g_pA[2][i];
        s4 += (double)g_pA[3][i];
    }
    __shared__ double sw[8];
    double vals[5] = {s0, s1, s2, s3, s4};
    double res[5];
    #pragma unroll
    for (int j = 0; j < 5; j++) {
        double v = vals[j];
        #pragma unroll
        for (int o = 16; o > 0; o >>= 1) v += __shfl_down_sync(0xffffffffu, v, o);
        if (lane == 0) sw[wid] = v;
        __syncthreads();
        v = (tid < 8) ? sw[tid] : 0.0;
        if (wid == 0) {
            #pragma unroll
            for (int o = 4; o > 0; o >>= 1) v += __shfl_down_sync(0xffffffffu, v, o);
        }
        res[j] = v;
        __syncthreads();
    }
    if (tid == 0) {
        float v0 = (float)(res[0] / (double)B);
        float v1 = (float)(res[1] / (double)B);
        float v2 = (float)(res[2] / (double)B);
        float v3 = (float)(res[3] / (double)B);
        float v4 = (float)(res[4] / (double)B);
        out[0]=v0; out[1]=v1; out[2]=v2; out[3]=v3; out[4]=v4;
        out[5] = (((v0 + v1) + v2) + v3) + v4;
        g_done = 0;
    }
    if (tid < MAXB) g_cnt[tid] = 0;
}

extern "C" void kernel_launch(void* const* d_in, const int* in_sizes, int n_in,
                              void* d_out, int out_size) {
    const float* preds   = (const float*)d_in[0];
    const float* targets = (const float*)d_in[1];
    const float* anchors = (const float*)d_in[2];
    float* out = (float*)d_out;

    int B = in_sizes[0] / (NCELL * REC);
    if (B > MAXB) B = MAXB;

    dim3 gA(KAB, B);
    kA<<<gA, KAT>>>(targets);
    dim3 gB(GBX, B);
    kB<<<gB, KBT>>>(preds, targets, anchors, out, B);
}